// round 1
// baseline (speedup 1.0000x reference)
#include <cuda_runtime.h>
#include <cuda_bf16.h>
#include <math.h>

#define Bx 8
#define Nx 4096
#define Ex 131072
#define Fx 64
#define ALPHA 0.2f

// ---------------- scratch (device globals; no allocations allowed) ----------
__device__ __align__(16) float g_Wh[Bx * Nx * Fx];     // 8 MB, [b][n][f]
__device__ __align__(16) float g_ssrc[Bx * Nx];        // 128 KB
__device__ __align__(16) float g_sdst[Bx * Nx];        // 128 KB
__device__ __align__(16) int   g_deg[Nx];
__device__ __align__(16) int   g_rowptr[Nx + 1];
__device__ __align__(16) int   g_cursor[Nx];
__device__ __align__(16) int   g_csr_dst[Ex];
__device__ __align__(16) float g_csr_w[Ex];

// ---------------- K0: zero degree histogram ---------------------------------
__global__ void k_zero() {
    int i = blockIdx.x * blockDim.x + threadIdx.x;
    if (i < Nx) g_deg[i] = 0;
}

// ---------------- K1: Wh = h @ W, plus s_src = Wh@a1, s_dst = Wh@a2 ---------
// 256 threads / block; 8 rows (b*N+n) per block; 1 warp per row; float2 per thread.
__global__ __launch_bounds__(256) void k_gemm(const float* __restrict__ h,
                                              const float* __restrict__ W,
                                              const float* __restrict__ a) {
    __shared__ float sW[64 * 64];   // 16 KB
    __shared__ float sh[8][64];     // 2 KB
    const int tid = threadIdx.x;
    const int row0 = blockIdx.x * 8;

    #pragma unroll
    for (int i = 0; i < 16; i++) sW[tid + i * 256] = W[tid + i * 256];
    #pragma unroll
    for (int i = 0; i < 2; i++) {
        int idx = tid + i * 256;                    // 0..511
        sh[idx >> 6][idx & 63] = h[row0 * 64 + idx];
    }
    __syncthreads();

    const int r  = tid >> 5;        // warp id = local row
    const int oo = tid & 31;        // lane -> output pair (2*oo, 2*oo+1)
    float2 acc = make_float2(0.f, 0.f);
    #pragma unroll
    for (int k = 0; k < 64; k++) {
        float hk = sh[r][k];
        float2 w2 = *(const float2*)&sW[k * 64 + oo * 2];
        acc.x = fmaf(hk, w2.x, acc.x);
        acc.y = fmaf(hk, w2.y, acc.y);
    }
    const int row = row0 + r;
    *(float2*)&g_Wh[row * 64 + oo * 2] = acc;

    // epilogue: dots with a1 = a[0:64], a2 = a[64:128]
    float p1 = acc.x * a[oo * 2]      + acc.y * a[oo * 2 + 1];
    float p2 = acc.x * a[64 + oo * 2] + acc.y * a[64 + oo * 2 + 1];
    #pragma unroll
    for (int s = 16; s > 0; s >>= 1) {
        p1 += __shfl_xor_sync(0xffffffffu, p1, s);
        p2 += __shfl_xor_sync(0xffffffffu, p2, s);
    }
    if (oo == 0) { g_ssrc[row] = p1; g_sdst[row] = p2; }
}

// ---------------- K2: degree histogram over src ------------------------------
__global__ void k_hist(const int* __restrict__ ei) {
    int e = blockIdx.x * blockDim.x + threadIdx.x;
    if (e < Ex) atomicAdd(&g_deg[ei[e]], 1);
}

// ---------------- K3: exclusive scan (4096 elems, 1 block of 1024) ----------
__global__ __launch_bounds__(1024) void k_scan() {
    __shared__ int wsum[32];
    const int tid  = threadIdx.x;
    const int lane = tid & 31;
    const int warp = tid >> 5;
    int4 d = *(const int4*)&g_deg[tid * 4];
    int t = d.x + d.y + d.z + d.w;
    int v = t;
    #pragma unroll
    for (int s = 1; s < 32; s <<= 1) {
        int u = __shfl_up_sync(0xffffffffu, v, s);
        if (lane >= s) v += u;
    }
    if (lane == 31) wsum[warp] = v;
    __syncthreads();
    if (warp == 0) {
        int wv = wsum[lane];
        #pragma unroll
        for (int s = 1; s < 32; s <<= 1) {
            int u = __shfl_up_sync(0xffffffffu, wv, s);
            if (lane >= s) wv += u;
        }
        wsum[lane] = wv;
    }
    __syncthreads();
    int base = (warp > 0 ? wsum[warp - 1] : 0) + (v - t);
    int idx = tid * 4;
    g_rowptr[idx]     = base;
    g_rowptr[idx + 1] = base + d.x;
    g_rowptr[idx + 2] = base + d.x + d.y;
    g_rowptr[idx + 3] = base + d.x + d.y + d.z;
    g_cursor[idx]     = base;
    g_cursor[idx + 1] = base + d.x;
    g_cursor[idx + 2] = base + d.x + d.y;
    g_cursor[idx + 3] = base + d.x + d.y + d.z;
    if (tid == 1023) g_rowptr[Nx] = wsum[31];
}

// ---------------- K4: scatter edges into CSR buckets -------------------------
__global__ void k_scatter(const int* __restrict__ ei, const float* __restrict__ ew) {
    int e = blockIdx.x * blockDim.x + threadIdx.x;
    if (e < Ex) {
        int s = ei[e];
        int pos = atomicAdd(&g_cursor[s], 1);
        g_csr_dst[pos] = ei[Ex + e];
        g_csr_w[pos]   = ew[e];
    }
}

// ---------------- K5: per-(b,node) softmax + aggregation (gather, no atomics)
// 1 warp per (b,node). Pass A: segment max (lane-parallel over edges).
// Pass B: chunked — lane-parallel exp, stage (ex, Wh row offset) in smem,
// then feature-parallel accumulate of Wh[dst] rows (float2 per lane).
__global__ __launch_bounds__(256) void k_agg(float* __restrict__ out) {
    __shared__ float sh_ex[8][32];
    __shared__ int   sh_off[8][32];
    const int tid  = threadIdx.x;
    const int lane = tid & 31;
    const int w    = tid >> 5;
    const int g    = blockIdx.x * 8 + w;    // = b*Nx + node
    const int node = g & (Nx - 1);
    const int b    = g >> 12;

    const int start = g_rowptr[node];
    const int end   = g_rowptr[node + 1];
    const float s1  = g_ssrc[g];
    const float* __restrict__ sdst_b = &g_sdst[b * Nx];
    const int base_b = b * Nx * Fx;

    // Pass A: segment max
    float m = -INFINITY;
    for (int j = start + lane; j < end; j += 32) {
        int dj = g_csr_dst[j];
        float raw = s1 + sdst_b[dj];
        float e = raw > 0.f ? raw : ALPHA * raw;
        e *= g_csr_w[j];
        m = fmaxf(m, e);
    }
    #pragma unroll
    for (int s = 16; s > 0; s >>= 1)
        m = fmaxf(m, __shfl_xor_sync(0xffffffffu, m, s));

    // Pass B: chunked accumulate
    float2 acc = make_float2(0.f, 0.f);
    float dsum = 0.f;
    for (int p = start; p < end; p += 32) {
        int j = p + lane;
        float ex = 0.f;
        int off = 0;
        if (j < end) {
            int dj = g_csr_dst[j];
            float raw = s1 + sdst_b[dj];
            float e = raw > 0.f ? raw : ALPHA * raw;
            e *= g_csr_w[j];
            ex = __expf(e - m);
            off = base_b + dj * Fx;
            dsum += ex;
        }
        sh_ex[w][lane]  = ex;
        sh_off[w][lane] = off;
        __syncwarp();
        const int cnt = min(32, end - p);
        if (cnt == 32) {
            #pragma unroll 8
            for (int t = 0; t < 32; t++) {
                float exv = sh_ex[w][t];
                float2 vv = *(const float2*)&g_Wh[sh_off[w][t] + lane * 2];
                acc.x = fmaf(exv, vv.x, acc.x);
                acc.y = fmaf(exv, vv.y, acc.y);
            }
        } else {
            for (int t = 0; t < cnt; t++) {
                float exv = sh_ex[w][t];
                float2 vv = *(const float2*)&g_Wh[sh_off[w][t] + lane * 2];
                acc.x = fmaf(exv, vv.x, acc.x);
                acc.y = fmaf(exv, vv.y, acc.y);
            }
        }
        __syncwarp();
    }
    #pragma unroll
    for (int s = 16; s > 0; s >>= 1)
        dsum += __shfl_xor_sync(0xffffffffu, dsum, s);

    float inv = (end > start) ? (1.0f / dsum) : 0.f;
    float h0 = acc.x * inv;
    float h1 = acc.y * inv;
    float o0 = h0 > 0.f ? h0 : expm1f(h0);
    float o1 = h1 > 0.f ? h1 : expm1f(h1);
    *(float2*)&out[g * 64 + lane * 2] = make_float2(o0, o1);
}

// ---------------- launch -----------------------------------------------------
extern "C" void kernel_launch(void* const* d_in, const int* in_sizes, int n_in,
                              void* d_out, int out_size) {
    const float* h  = (const float*)d_in[0];
    const int*   ei = (const int*)d_in[1];
    const float* ew = (const float*)d_in[2];
    const float* W  = (const float*)d_in[3];
    const float* a  = (const float*)d_in[4];
    float* out = (float*)d_out;

    k_zero<<<(Nx + 255) / 256, 256>>>();
    k_gemm<<<(Bx * Nx) / 8, 256>>>(h, W, a);
    k_hist<<<(Ex + 255) / 256, 256>>>(ei);
    k_scan<<<1, 1024>>>();
    k_scatter<<<(Ex + 255) / 256, 256>>>(ei, ew);
    k_agg<<<(Bx * Nx) / 8, 256>>>(out);
}

// round 2
// speedup vs baseline: 1.0042x; 1.0042x over previous
#include <cuda_runtime.h>
#include <cuda_bf16.h>
#include <math.h>

#define Bx 8
#define Nx 4096
#define Ex 131072
#define Fx 64
#define CAP 128
#define ALPHA 0.2f

// ---------------- scratch (device globals; zero-initialized at load) --------
__device__ __align__(16) float g_Wh[Bx * Nx * Fx];      // 8 MB, [b][n][f]
__device__ __align__(16) float g_ssrc[Bx * Nx];
__device__ __align__(16) float g_sdst[Bx * Nx];
__device__ __align__(16) int   g_cnt[Nx];               // reset by k_agg each run
__device__ __align__(16) int   g_bkt_dst[Nx * CAP];     // 2 MB
__device__ __align__(16) float g_bkt_w[Nx * CAP];       // 2 MB

// ---------------- K1: Wh = h@W (+ s_src/s_dst dots) + edge bucketing --------
// 1024 blocks x 256 threads. 32 rows/block; warp handles 4 rows so the W
// float2 register is reused 4x (cuts LDS traffic 4x -> FMA-bound).
// Threads tid<128 additionally bucket 128 edges (atomic, order-free).
__global__ __launch_bounds__(256) void k_gemm(const float* __restrict__ h,
                                              const float* __restrict__ W,
                                              const float* __restrict__ a,
                                              const int* __restrict__ ei,
                                              const float* __restrict__ ew) {
    __shared__ float sW[64 * 64];     // 16 KB
    __shared__ float sh[32][64];      // 8 KB
    const int tid = threadIdx.x;

    // edge bucketing: 128 edges per block (1024*128 = 131072 = Ex)
    if (tid < 128) {
        int e = blockIdx.x * 128 + tid;
        int s = ei[e];
        int d = ei[Ex + e];
        float w = ew[e];
        int pos = atomicAdd(&g_cnt[s], 1);
        if (pos < CAP) {
            g_bkt_dst[s * CAP + pos] = d;
            g_bkt_w[s * CAP + pos]   = w;
        }
    }

    const int row0 = blockIdx.x * 32;
    #pragma unroll
    for (int i = 0; i < 16; i++) sW[tid + i * 256] = W[tid + i * 256];
    #pragma unroll
    for (int i = 0; i < 8; i++) {
        int idx = tid + i * 256;                 // 0..2047
        sh[idx >> 6][idx & 63] = h[row0 * 64 + idx];
    }
    __syncthreads();

    const int w  = tid >> 5;          // warp id -> 4 rows
    const int oo = tid & 31;          // lane -> output pair
    const int r0 = w * 4;
    float2 acc0 = make_float2(0.f, 0.f), acc1 = acc0, acc2 = acc0, acc3 = acc0;
    #pragma unroll
    for (int k = 0; k < 64; k++) {
        float2 w2 = *(const float2*)&sW[k * 64 + oo * 2];
        float h0 = sh[r0 + 0][k];
        float h1 = sh[r0 + 1][k];
        float h2 = sh[r0 + 2][k];
        float h3 = sh[r0 + 3][k];
        acc0.x = fmaf(h0, w2.x, acc0.x); acc0.y = fmaf(h0, w2.y, acc0.y);
        acc1.x = fmaf(h1, w2.x, acc1.x); acc1.y = fmaf(h1, w2.y, acc1.y);
        acc2.x = fmaf(h2, w2.x, acc2.x); acc2.y = fmaf(h2, w2.y, acc2.y);
        acc3.x = fmaf(h3, w2.x, acc3.x); acc3.y = fmaf(h3, w2.y, acc3.y);
    }

    const float a1x = a[oo * 2],      a1y = a[oo * 2 + 1];
    const float a2x = a[64 + oo * 2], a2y = a[64 + oo * 2 + 1];
    float2 accs[4] = {acc0, acc1, acc2, acc3};
    #pragma unroll
    for (int i = 0; i < 4; i++) {
        const int row = row0 + r0 + i;
        *(float2*)&g_Wh[row * 64 + oo * 2] = accs[i];
        float p1 = accs[i].x * a1x + accs[i].y * a1y;
        float p2 = accs[i].x * a2x + accs[i].y * a2y;
        #pragma unroll
        for (int s = 16; s > 0; s >>= 1) {
            p1 += __shfl_xor_sync(0xffffffffu, p1, s);
            p2 += __shfl_xor_sync(0xffffffffu, p2, s);
        }
        if (oo == 0) { g_ssrc[row] = p1; g_sdst[row] = p2; }
    }
}

// ---------------- K2: softmax + aggregation, block per node ------------------
// 256 threads = 8 warps = 8 batches. Edge list cached in smem once.
// Single gather pass: e kept in <=4 regs/lane, warp-max, exp, then
// feature-parallel Wh-row accumulation with shfl broadcast of ex.
__global__ __launch_bounds__(256) void k_agg(float* __restrict__ out) {
    __shared__ int   sh_dst[CAP];
    __shared__ float sh_w[CAP];
    __shared__ int   sh_cnt;
    const int node = blockIdx.x;
    const int tid  = threadIdx.x;
    const int lane = tid & 31;
    const int b    = tid >> 5;

    if (tid == 0) {
        int c = g_cnt[node];
        sh_cnt = (c < CAP) ? c : CAP;
        g_cnt[node] = 0;                       // reset for next graph replay
    }
    __syncthreads();
    const int deg = sh_cnt;

    for (int j = tid; j < deg; j += 256) {
        sh_dst[j] = g_bkt_dst[node * CAP + j];
        sh_w[j]   = g_bkt_w[node * CAP + j];
    }
    __syncthreads();

    const float s1 = g_ssrc[b * Nx + node];
    const float* __restrict__ sdst_b = &g_sdst[b * Nx];
    const float* __restrict__ WhB    = &g_Wh[b * Nx * Fx];

    // gather e per lane (up to 4 chunks), running max
    float ev[4];
    float m = -INFINITY;
    const int nch = (deg + 31) >> 5;
    #pragma unroll
    for (int c = 0; c < 4; c++) {
        float e = -INFINITY;
        int j = c * 32 + lane;
        if (c < nch && j < deg) {
            float raw = s1 + __ldg(&sdst_b[sh_dst[j]]);
            e = raw > 0.f ? raw : ALPHA * raw;
            e *= sh_w[j];
        }
        ev[c] = e;
        m = fmaxf(m, e);
    }
    #pragma unroll
    for (int s = 16; s > 0; s >>= 1)
        m = fmaxf(m, __shfl_xor_sync(0xffffffffu, m, s));

    // exp + denom (invalid lanes: exp(-inf - m) handled explicitly as 0)
    float dsum = 0.f;
    #pragma unroll
    for (int c = 0; c < 4; c++) {
        float e = (deg > 0 && ev[c] != -INFINITY) ? __expf(ev[c] - m) : 0.f;
        ev[c] = e;
        dsum += e;
    }
    #pragma unroll
    for (int s = 16; s > 0; s >>= 1)
        dsum += __shfl_xor_sync(0xffffffffu, dsum, s);

    // feature-parallel accumulation: lane owns 2 features
    float2 acc = make_float2(0.f, 0.f);
    #pragma unroll
    for (int c = 0; c < 4; c++) {
        if (c * 32 >= deg) break;
        const float evc = ev[c];
        const int lim = min(32, deg - c * 32);
        if (lim == 32) {
            #pragma unroll 8
            for (int tt = 0; tt < 32; tt++) {
                float exv = __shfl_sync(0xffffffffu, evc, tt);
                int d = sh_dst[c * 32 + tt];
                float2 v = *(const float2*)&WhB[d * 64 + lane * 2];
                acc.x = fmaf(exv, v.x, acc.x);
                acc.y = fmaf(exv, v.y, acc.y);
            }
        } else {
            for (int tt = 0; tt < lim; tt++) {
                float exv = __shfl_sync(0xffffffffu, evc, tt);
                int d = sh_dst[c * 32 + tt];
                float2 v = *(const float2*)&WhB[d * 64 + lane * 2];
                acc.x = fmaf(exv, v.x, acc.x);
                acc.y = fmaf(exv, v.y, acc.y);
            }
        }
    }

    const float inv = (deg > 0) ? (1.0f / dsum) : 0.f;
    float h0 = acc.x * inv;
    float h1 = acc.y * inv;
    float o0 = h0 > 0.f ? h0 : expm1f(h0);
    float o1 = h1 > 0.f ? h1 : expm1f(h1);
    *(float2*)&out[(b * Nx + node) * 64 + lane * 2] = make_float2(o0, o1);
}

// ---------------- launch -----------------------------------------------------
extern "C" void kernel_launch(void* const* d_in, const int* in_sizes, int n_in,
                              void* d_out, int out_size) {
    const float* h  = (const float*)d_in[0];
    const int*   ei = (const int*)d_in[1];
    const float* ew = (const float*)d_in[2];
    const float* W  = (const float*)d_in[3];
    const float* a  = (const float*)d_in[4];
    float* out = (float*)d_out;

    k_gemm<<<(Bx * Nx) / 32, 256>>>(h, W, a, ei, ew);
    k_agg<<<Nx, 256>>>(out);
}